// round 8
// baseline (speedup 1.0000x reference)
#include <cuda_runtime.h>
#include <cuda_bf16.h>
#include <cstdint>

// Problem constants
static constexpr int Bz = 64;     // batch
static constexpr int Sz = 1024;   // seq len
static constexpr int Hz = 256;    // hidden
static constexpr int G3 = 768;    // 3*H gate rows

// Recurrence geometry: 16 clusters x 8 CTAs = 128 CTAs; each cluster = 4 batches,
// each CTA owns 32 h-units (96 gate rows of W_hh in smem).
// Row layout: 256 k-floats stored as [0..127][pad4][128..255], stride LDW=264.
// -> (u stride mod 32 banks) = 8, (k-half offset mod 32) = 4: the 8 distinct
// (u,kh) chunks per warp cover all 32 banks -> conflict-free LDS.128.
static constexpr int LDW = 264;
static constexpr int SMEM_FLOATS = 96 * LDW + 96 + 2 * 4 * LDW; // W + bias + 2x h
static constexpr int SMEM_BYTES = SMEM_FLOATS * 4;              // 110,208 B

// Scratch for precomputed input-side gate projections xg = x @ W_ih^T + b_ih  [B,S,3H]
__device__ float g_xg[(size_t)Bz * Sz * G3];

typedef unsigned long long u64;

__device__ __forceinline__ u64 fma2(u64 a, u64 b, u64 c) {
    u64 d;
    asm("fma.rn.f32x2 %0, %1, %2, %3;" : "=l"(d) : "l"(a), "l"(b), "l"(c));
    return d;
}
__device__ __forceinline__ float f2lo(u64 v) { return __uint_as_float((unsigned)v); }
__device__ __forceinline__ float f2hi(u64 v) { return __uint_as_float((unsigned)(v >> 32)); }
__device__ __forceinline__ u64 dup2(float a) {
    unsigned ai = __float_as_uint(a);
    u64 d;
    asm("mov.b64 %0, {%1, %2};" : "=l"(d) : "r"(ai), "r"(ai));
    return d;
}

// ---------------------------------------------------------------------------
// GEMM: g_xg[m, 0:768] = A[m, 0:256] @ W[768, 256]^T + bias   (unchanged)
// ---------------------------------------------------------------------------
__global__ __launch_bounds__(256) void gemm_nt_bias(
    const float* __restrict__ A, int lda,
    const float* __restrict__ W,
    const float* __restrict__ bias)
{
    __shared__ __align__(16) float As[32][68];  // As[k][m]
    __shared__ __align__(16) float Ws[32][68];  // Ws[k][n]

    const int tid = threadIdx.x;
    const int tx = tid & 15;
    const int ty = tid >> 4;
    const int m0 = blockIdx.y * 64;
    const int n0 = blockIdx.x * 64;

    u64 c00 = 0, c01 = 0, c10 = 0, c11 = 0, c20 = 0, c21 = 0, c30 = 0, c31 = 0;

    const int lrow = tid >> 3;
    const int lc4  = tid & 7;

    for (int k0 = 0; k0 < 256; k0 += 32) {
#pragma unroll
        for (int h = 0; h < 2; ++h) {
            const int row = lrow + h * 32;
            float4 va = *(const float4*)(A + (size_t)(m0 + row) * lda + k0 + lc4 * 4);
            As[lc4 * 4 + 0][row] = va.x;
            As[lc4 * 4 + 1][row] = va.y;
            As[lc4 * 4 + 2][row] = va.z;
            As[lc4 * 4 + 3][row] = va.w;
            float4 vw = *(const float4*)(W + (size_t)(n0 + row) * 256 + k0 + lc4 * 4);
            Ws[lc4 * 4 + 0][row] = vw.x;
            Ws[lc4 * 4 + 1][row] = vw.y;
            Ws[lc4 * 4 + 2][row] = vw.z;
            Ws[lc4 * 4 + 3][row] = vw.w;
        }
        __syncthreads();
#pragma unroll 8
        for (int kk = 0; kk < 32; ++kk) {
            float4 a4 = *(const float4*)&As[kk][ty * 4];
            ulonglong2 w4 = *(const ulonglong2*)&Ws[kk][tx * 4];
            u64 d0 = dup2(a4.x), d1 = dup2(a4.y), d2 = dup2(a4.z), d3 = dup2(a4.w);
            c00 = fma2(d0, w4.x, c00); c01 = fma2(d0, w4.y, c01);
            c10 = fma2(d1, w4.x, c10); c11 = fma2(d1, w4.y, c11);
            c20 = fma2(d2, w4.x, c20); c21 = fma2(d2, w4.y, c21);
            c30 = fma2(d3, w4.x, c30); c31 = fma2(d3, w4.y, c31);
        }
        __syncthreads();
    }

    const float4 bb = *(const float4*)(bias + n0 + tx * 4);
    float* Cbase = g_xg + (size_t)(m0 + ty * 4) * G3 + n0 + tx * 4;
    {
        float4 o;
        o.x = f2lo(c00) + bb.x; o.y = f2hi(c00) + bb.y;
        o.z = f2lo(c01) + bb.z; o.w = f2hi(c01) + bb.w;
        *(float4*)(Cbase + 0 * G3) = o;
    }
    {
        float4 o;
        o.x = f2lo(c10) + bb.x; o.y = f2hi(c10) + bb.y;
        o.z = f2lo(c11) + bb.z; o.w = f2hi(c11) + bb.w;
        *(float4*)(Cbase + 1 * G3) = o;
    }
    {
        float4 o;
        o.x = f2lo(c20) + bb.x; o.y = f2hi(c20) + bb.y;
        o.z = f2lo(c21) + bb.z; o.w = f2hi(c21) + bb.w;
        *(float4*)(Cbase + 2 * G3) = o;
    }
    {
        float4 o;
        o.x = f2lo(c30) + bb.x; o.y = f2hi(c30) + bb.y;
        o.z = f2lo(c31) + bb.z; o.w = f2hi(c31) + bb.w;
        *(float4*)(Cbase + 3 * G3) = o;
    }
}

// ---------------------------------------------------------------------------
// Recurrence: cluster of 8 CTAs handles 4 batch sequences.
// CTA rank owns h-units [32*rank, 32*rank+32). Thread mapping (256 threads):
//   kh    = tid & 1        (K half: [0,128) or [128,256))
//   b_loc = (tid >> 1) & 3 (batch within cluster)
//   u_loc = tid >> 3       (0..31, h-unit within CTA)
// Each lane computes 3 half-dots; pair lanes (tid^1) combine via shfl.xor(1).
// Both lanes compute the gates; kh0 stores DSMEM peers 0-3 + outA, kh1 stores
// peers 4-7 + outB. One barrier.cluster per step (release/acquire for the
// st.shared::cluster writes into the double-buffered h state).
// ---------------------------------------------------------------------------
__global__ __launch_bounds__(256, 1) __cluster_dims__(8, 1, 1)
void gru_recur(const float* __restrict__ Whh, const float* __restrict__ bhh,
               float* __restrict__ outA, int ldA,
               float* __restrict__ outB, int ldB)
{
    extern __shared__ __align__(16) float sm[];
    float* sW = sm;                      // [96][LDW]
    float* sB = sm + 96 * LDW;           // [96]
    float* sH = sm + 96 * LDW + 96;      // [2][4][LDW]

    const int tid = threadIdx.x;
    uint32_t rank;
    asm("mov.u32 %0, %%cluster_ctarank;" : "=r"(rank));
    const int kh    = tid & 1;
    const int b_loc = (tid >> 1) & 3;
    const int u_loc = tid >> 3;
    const int u_glob = (int)rank * 32 + u_loc;
    const int posu = u_glob + ((u_glob >= 128) ? 4 : 0);  // padded h position
    const int batch = (blockIdx.x >> 3) * 4 + b_loc;

    // Load this CTA's W_hh slice (rows g*256 + rank*32 + u) into padded smem.
    for (int idx = tid; idx < 96 * 64; idx += 256) {
        int r = idx >> 6, k4 = idx & 63;
        int g = r >> 5, u = r & 31;
        int grow = g * 256 + (int)rank * 32 + u;
        float4 v = ((const float4*)(Whh + (size_t)grow * 256))[k4];
        int doff = k4 * 4 + ((k4 >= 32) ? 4 : 0);  // asymmetric pad between k-halves
        *(float4*)(sW + (size_t)r * LDW + doff) = v;
    }
    if (tid < 96) {
        int g = tid >> 5, u = tid & 31;
        sB[tid] = bhh[g * 256 + (int)rank * 32 + u];
    }
    for (int i = tid; i < 2 * 4 * LDW; i += 256) sH[i] = 0.f;
    __syncthreads();
    asm volatile("barrier.cluster.arrive.aligned;" ::: "memory");
    asm volatile("barrier.cluster.wait.aligned;" ::: "memory");

    const int khoff = kh * 132;  // float offset of this lane's k-half
    const ulonglong2* wr = (const ulonglong2*)(sW + (size_t)(u_loc) * LDW + khoff);
    const ulonglong2* wz = (const ulonglong2*)(sW + (size_t)(32 + u_loc) * LDW + khoff);
    const ulonglong2* wn = (const ulonglong2*)(sW + (size_t)(64 + u_loc) * LDW + khoff);
    const float bhr = sB[u_loc], bhz = sB[32 + u_loc], bhn = sB[64 + u_loc];

    const float* xgp = g_xg + ((size_t)batch * Sz) * G3 + u_glob;
    size_t oa = ((size_t)batch * Sz) * (size_t)ldA + u_glob;
    size_t ob = ((size_t)batch * Sz) * (size_t)ldB + u_glob;

    // Precompute the 8 peer base addresses of sH (hoist mapa out of the loop).
    uint32_t sH_u32;
    {
        uint32_t b_;
        asm("{ .reg .u64 t; cvta.to.shared.u64 t, %1; cvt.u32.u64 %0, t; }"
            : "=r"(b_) : "l"(sm));
        sH_u32 = b_ + (uint32_t)((96 * LDW + 96) * 4);
    }
    uint32_t peer[4];
#pragma unroll
    for (int p = 0; p < 4; ++p) {
        uint32_t ra;
        uint32_t pr = (uint32_t)(p + kh * 4);  // kh0 -> CTAs 0-3, kh1 -> CTAs 4-7
        asm("mapa.shared::cluster.u32 %0, %1, %2;" : "=r"(ra) : "r"(sH_u32), "r"(pr));
        peer[p] = ra;
    }

    const bool doB = (outB != nullptr);
    int cur = 0;
    for (int s = 0; s < Sz; ++s) {
        // Input-side gate values (issued before the dot loop; latency hidden).
        const float xr = __ldg(xgp);
        const float xz = __ldg(xgp + 256);
        const float xn = __ldg(xgp + 512);

        const ulonglong2* hv =
            (const ulonglong2*)(sH + (size_t)(cur * 4 + b_loc) * LDW + khoff);
        u64 ar = 0, az = 0, an = 0;
#pragma unroll 8
        for (int kk = 0; kk < 32; ++kk) {
            ulonglong2 h4 = hv[kk];
            ulonglong2 w;
            w = wr[kk]; ar = fma2(w.x, h4.x, ar); ar = fma2(w.y, h4.y, ar);
            w = wz[kk]; az = fma2(w.x, h4.x, az); az = fma2(w.y, h4.y, az);
            w = wn[kk]; an = fma2(w.x, h4.x, an); an = fma2(w.y, h4.y, an);
        }
        // Half-dot partials -> full dots via pair-lane exchange.
        float pr_ = f2lo(ar) + f2hi(ar);
        float pz_ = f2lo(az) + f2hi(az);
        float pn_ = f2lo(an) + f2hi(an);
        pr_ += __shfl_xor_sync(0xFFFFFFFFu, pr_, 1);
        pz_ += __shfl_xor_sync(0xFFFFFFFFu, pz_, 1);
        pn_ += __shfl_xor_sync(0xFFFFFFFFu, pn_, 1);

        const float hr = pr_ + bhr;
        const float hz = pz_ + bhz;
        const float hn = pn_ + bhn;
        const float hprev = sH[(size_t)(cur * 4 + b_loc) * LDW + posu];

        const float rg = 1.f / (1.f + expf(-(xr + hr)));
        const float zg = 1.f / (1.f + expf(-(xz + hz)));
        const float ng = tanhf(xn + rg * hn);
        const float hnew = ng + zg * (hprev - ng);

        // Broadcast new h into all 8 CTAs' next-step buffer (4 peers per lane).
        const uint32_t off =
            (uint32_t)((((cur ^ 1) * 4 + b_loc) * LDW + posu) * 4);
#pragma unroll
        for (int p = 0; p < 4; ++p) {
            asm volatile("st.shared::cluster.f32 [%0], %1;"
                         :: "r"(peer[p] + off), "f"(hnew) : "memory");
        }

        if (kh == 0) {
            outA[oa] = hnew;
        } else if (doB) {
            outB[ob] = hnew;
        }
        oa += (size_t)ldA;
        ob += (size_t)ldB;
        xgp += G3;

        // Release my DSMEM writes / acquire peers' writes for the next step.
        asm volatile("barrier.cluster.arrive.aligned;" ::: "memory");
        asm volatile("barrier.cluster.wait.aligned;" ::: "memory");
        cur ^= 1;
    }
}

// ---------------------------------------------------------------------------
// Launch: gemm(xg0) -> recur L0 (h1 into concat[:, :, 0:256])
//         gemm(xg1 from h1) -> recur L1 (h2 into out_h2 and concat[:, :, 256:512])
// Output layout: [h2 (B,S,H)] then [concat(h1,h2) (B,S,2H)].
// ---------------------------------------------------------------------------
extern "C" void kernel_launch(void* const* d_in, const int* in_sizes, int n_in,
                              void* d_out, int out_size)
{
    (void)in_sizes; (void)n_in; (void)out_size;
    const float* inputs = (const float*)d_in[0];
    const float* W_ih0  = (const float*)d_in[1];
    const float* W_hh0  = (const float*)d_in[2];
    const float* b_ih0  = (const float*)d_in[3];
    const float* b_hh0  = (const float*)d_in[4];
    const float* W_ih1  = (const float*)d_in[5];
    const float* W_hh1  = (const float*)d_in[6];
    const float* b_ih1  = (const float*)d_in[7];
    const float* b_hh1  = (const float*)d_in[8];

    float* out_h2  = (float*)d_out;                            // [B,S,H]
    float* out_cat = out_h2 + (size_t)Bz * Sz * Hz;            // [B,S,2H]

    cudaFuncSetAttribute(gru_recur, cudaFuncAttributeMaxDynamicSharedMemorySize,
                         SMEM_BYTES);

    dim3 ggrid(G3 / 64, (Bz * Sz) / 64);  // (12, 1024)

    // Layer 0
    gemm_nt_bias<<<ggrid, 256>>>(inputs, 256, W_ih0, b_ih0);
    gru_recur<<<128, 256, SMEM_BYTES>>>(W_hh0, b_hh0,
                                        out_cat, 2 * Hz,       // h1 -> concat[:, :, 0:H]
                                        nullptr, 0);
    // Layer 1 (input = h1, strided inside concat)
    gemm_nt_bias<<<ggrid, 256>>>(out_cat, 2 * Hz, W_ih1, b_ih1);
    gru_recur<<<128, 256, SMEM_BYTES>>>(W_hh1, b_hh1,
                                        out_cat + Hz, 2 * Hz,  // h2 -> concat[:, :, H:2H]
                                        out_h2, Hz);           // h2 -> primary output
}

// round 11
// speedup vs baseline: 1.8396x; 1.8396x over previous
#include <cuda_runtime.h>
#include <cuda_bf16.h>
#include <cstdint>

// Problem constants
static constexpr int Bz = 64;     // batch
static constexpr int Sz = 1024;   // seq len
static constexpr int Hz = 256;    // hidden
static constexpr int G3 = 768;    // 3*H gate rows

// Recurrence geometry: 32 clusters x 4 CTAs = 128 CTAs; each cluster = 2 batches,
// each CTA owns 64 h-units (192 gate rows of W_hh in smem), 512 threads.
// Thread map: kq = tid&3 (k-quarter), b_loc = (tid>>2)&1, u_loc = tid>>3.
//
// Row layout (weights AND h): 256 k-floats as 4 chunks of 68 (64 data + 4 pad),
// stride LDW = 272 floats. Chunk(16B-unit) index mod 8:
//   w:  u_loc*68 + kq*17  -> {0,4}x{0,1,2,3} + ... = uniform 2-way (16 chunks/warp)
//   h:  brow*68 + kq*17   -> 8 distinct chunks/warp = conflict-free (4-way bcast)
static constexpr int LDW = 272;
static constexpr int SMEM_FLOATS = 192 * LDW + 192 + 2 * 2 * LDW; // W + bias + 2-phase h
static constexpr int SMEM_BYTES = SMEM_FLOATS * 4;                // 214,016 B

// Scratch for precomputed input-side gate projections xg = x @ W_ih^T + b_ih  [B,S,3H]
__device__ float g_xg[(size_t)Bz * Sz * G3];

typedef unsigned long long u64;

__device__ __forceinline__ u64 fma2(u64 a, u64 b, u64 c) {
    u64 d;
    asm("fma.rn.f32x2 %0, %1, %2, %3;" : "=l"(d) : "l"(a), "l"(b), "l"(c));
    return d;
}
__device__ __forceinline__ float f2lo(u64 v) { return __uint_as_float((unsigned)v); }
__device__ __forceinline__ float f2hi(u64 v) { return __uint_as_float((unsigned)(v >> 32)); }
__device__ __forceinline__ u64 dup2(float a) {
    unsigned ai = __float_as_uint(a);
    u64 d;
    asm("mov.b64 %0, {%1, %2};" : "=l"(d) : "r"(ai), "r"(ai));
    return d;
}

// ---------------------------------------------------------------------------
// GEMM: g_xg[m, 0:768] = A[m, 0:256] @ W[768, 256]^T + bias   (unchanged)
// ---------------------------------------------------------------------------
__global__ __launch_bounds__(256) void gemm_nt_bias(
    const float* __restrict__ A, int lda,
    const float* __restrict__ W,
    const float* __restrict__ bias)
{
    __shared__ __align__(16) float As[32][68];  // As[k][m]
    __shared__ __align__(16) float Ws[32][68];  // Ws[k][n]

    const int tid = threadIdx.x;
    const int tx = tid & 15;
    const int ty = tid >> 4;
    const int m0 = blockIdx.y * 64;
    const int n0 = blockIdx.x * 64;

    u64 c00 = 0, c01 = 0, c10 = 0, c11 = 0, c20 = 0, c21 = 0, c30 = 0, c31 = 0;

    const int lrow = tid >> 3;
    const int lc4  = tid & 7;

    for (int k0 = 0; k0 < 256; k0 += 32) {
#pragma unroll
        for (int h = 0; h < 2; ++h) {
            const int row = lrow + h * 32;
            float4 va = *(const float4*)(A + (size_t)(m0 + row) * lda + k0 + lc4 * 4);
            As[lc4 * 4 + 0][row] = va.x;
            As[lc4 * 4 + 1][row] = va.y;
            As[lc4 * 4 + 2][row] = va.z;
            As[lc4 * 4 + 3][row] = va.w;
            float4 vw = *(const float4*)(W + (size_t)(n0 + row) * 256 + k0 + lc4 * 4);
            Ws[lc4 * 4 + 0][row] = vw.x;
            Ws[lc4 * 4 + 1][row] = vw.y;
            Ws[lc4 * 4 + 2][row] = vw.z;
            Ws[lc4 * 4 + 3][row] = vw.w;
        }
        __syncthreads();
#pragma unroll 8
        for (int kk = 0; kk < 32; ++kk) {
            float4 a4 = *(const float4*)&As[kk][ty * 4];
            ulonglong2 w4 = *(const ulonglong2*)&Ws[kk][tx * 4];
            u64 d0 = dup2(a4.x), d1 = dup2(a4.y), d2 = dup2(a4.z), d3 = dup2(a4.w);
            c00 = fma2(d0, w4.x, c00); c01 = fma2(d0, w4.y, c01);
            c10 = fma2(d1, w4.x, c10); c11 = fma2(d1, w4.y, c11);
            c20 = fma2(d2, w4.x, c20); c21 = fma2(d2, w4.y, c21);
            c30 = fma2(d3, w4.x, c30); c31 = fma2(d3, w4.y, c31);
        }
        __syncthreads();
    }

    const float4 bb = *(const float4*)(bias + n0 + tx * 4);
    float* Cbase = g_xg + (size_t)(m0 + ty * 4) * G3 + n0 + tx * 4;
    {
        float4 o;
        o.x = f2lo(c00) + bb.x; o.y = f2hi(c00) + bb.y;
        o.z = f2lo(c01) + bb.z; o.w = f2hi(c01) + bb.w;
        *(float4*)(Cbase + 0 * G3) = o;
    }
    {
        float4 o;
        o.x = f2lo(c10) + bb.x; o.y = f2hi(c10) + bb.y;
        o.z = f2lo(c11) + bb.z; o.w = f2hi(c11) + bb.w;
        *(float4*)(Cbase + 1 * G3) = o;
    }
    {
        float4 o;
        o.x = f2lo(c20) + bb.x; o.y = f2hi(c20) + bb.y;
        o.z = f2lo(c21) + bb.z; o.w = f2hi(c21) + bb.w;
        *(float4*)(Cbase + 2 * G3) = o;
    }
    {
        float4 o;
        o.x = f2lo(c30) + bb.x; o.y = f2hi(c30) + bb.y;
        o.z = f2lo(c31) + bb.z; o.w = f2hi(c31) + bb.w;
        *(float4*)(Cbase + 3 * G3) = o;
    }
}

// Map k-position j (0..255) to padded float offset within a row.
__device__ __forceinline__ int padpos(int j) { return (j >> 6) * 68 + (j & 63); }

// ---------------------------------------------------------------------------
// Recurrence: 4-CTA cluster handles 2 batch sequences. CTA rank owns h-units
// [64*rank, 64*rank+64). 512 threads: kq = tid&3 computes the k-quarter
// partial dot for (u_loc, b_loc); two shfl.xor rounds give the full dots to
// all 4 kq lanes, which redundantly compute the gates. Lane kq stores hnew
// into peer CTA kq's next-phase h buffer (1 DSMEM store/thread); kq0 stores
// outA, kq1 stores outB. One 4-CTA barrier.cluster per step.
// ---------------------------------------------------------------------------
__global__ __launch_bounds__(512, 1) __cluster_dims__(4, 1, 1)
void gru_recur(const float* __restrict__ Whh, const float* __restrict__ bhh,
               float* __restrict__ outA, int ldA,
               float* __restrict__ outB, int ldB)
{
    extern __shared__ __align__(16) float sm[];
    float* sW = sm;                       // [192][LDW]
    float* sB = sm + 192 * LDW;           // [192]
    float* sH = sm + 192 * LDW + 192;     // [2 phase][2 batch][LDW]

    const int tid = threadIdx.x;
    uint32_t rank;
    asm("mov.u32 %0, %%cluster_ctarank;" : "=r"(rank));
    const int kq    = tid & 3;
    const int b_loc = (tid >> 2) & 1;
    const int u_loc = tid >> 3;           // 0..63
    const int u_glob = (int)rank * 64 + u_loc;
    const int posu = padpos(u_glob);
    const int batch = (blockIdx.x >> 2) * 2 + b_loc;

    // Load this CTA's W_hh slice (rows g*256 + rank*64 + u) into padded smem.
    for (int idx = tid; idx < 192 * 64; idx += 512) {
        int r = idx >> 6, k4 = idx & 63;              // k4 = float4 index 0..63
        int g = r >> 6, u = r & 63;
        int grow = g * 256 + (int)rank * 64 + u;
        float4 v = ((const float4*)(Whh + (size_t)grow * 256))[k4];
        int doff = (k4 >> 4) * 68 + (k4 & 15) * 4;    // padded chunk layout
        *(float4*)(sW + (size_t)r * LDW + doff) = v;
    }
    if (tid < 192) {
        int g = tid >> 6, u = tid & 63;
        sB[tid] = bhh[g * 256 + (int)rank * 64 + u];
    }
    for (int i = tid; i < 2 * 2 * LDW; i += 512) sH[i] = 0.f;
    __syncthreads();
    asm volatile("barrier.cluster.arrive.aligned;" ::: "memory");
    asm volatile("barrier.cluster.wait.aligned;" ::: "memory");

    const int khoff = kq * 68;            // float offset of this lane's k-quarter
    const ulonglong2* wr = (const ulonglong2*)(sW + (size_t)(u_loc) * LDW + khoff);
    const ulonglong2* wz = (const ulonglong2*)(sW + (size_t)(64 + u_loc) * LDW + khoff);
    const ulonglong2* wn = (const ulonglong2*)(sW + (size_t)(128 + u_loc) * LDW + khoff);
    const float bhr = sB[u_loc], bhz = sB[64 + u_loc], bhn = sB[128 + u_loc];

    const float* xgp = g_xg + ((size_t)batch * Sz) * G3 + u_glob;
    size_t oa = ((size_t)batch * Sz) * (size_t)ldA + u_glob;
    size_t ob = ((size_t)batch * Sz) * (size_t)ldB + u_glob;

    // Peer base address of sH in CTA `kq` (hoist mapa out of the loop).
    uint32_t peer;
    {
        uint32_t b_;
        asm("{ .reg .u64 t; cvta.to.shared.u64 t, %1; cvt.u32.u64 %0, t; }"
            : "=r"(b_) : "l"(sm));
        uint32_t sH_u32 = b_ + (uint32_t)((192 * LDW + 192) * 4);
        asm("mapa.shared::cluster.u32 %0, %1, %2;"
            : "=r"(peer) : "r"(sH_u32), "r"((uint32_t)kq));
    }

    const bool doB = (outB != nullptr);
    int cur = 0;
    for (int s = 0; s < Sz; ++s) {
        // Input-side gate values (issued early; latency hidden by dot loop).
        const float xr = __ldg(xgp);
        const float xz = __ldg(xgp + 256);
        const float xn = __ldg(xgp + 512);

        const ulonglong2* hv =
            (const ulonglong2*)(sH + (size_t)(cur * 2 + b_loc) * LDW + khoff);
        u64 ar = 0, az = 0, an = 0;
#pragma unroll
        for (int kk = 0; kk < 16; ++kk) {
            ulonglong2 h4 = hv[kk];
            ulonglong2 w;
            w = wr[kk]; ar = fma2(w.x, h4.x, ar); ar = fma2(w.y, h4.y, ar);
            w = wz[kk]; az = fma2(w.x, h4.x, az); az = fma2(w.y, h4.y, az);
            w = wn[kk]; an = fma2(w.x, h4.x, an); an = fma2(w.y, h4.y, an);
        }
        // Quarter-dot partials -> full dots via 2-round butterfly over kq lanes.
        float pr_ = f2lo(ar) + f2hi(ar);
        float pz_ = f2lo(az) + f2hi(az);
        float pn_ = f2lo(an) + f2hi(an);
        pr_ += __shfl_xor_sync(0xFFFFFFFFu, pr_, 1);
        pz_ += __shfl_xor_sync(0xFFFFFFFFu, pz_, 1);
        pn_ += __shfl_xor_sync(0xFFFFFFFFu, pn_, 1);
        pr_ += __shfl_xor_sync(0xFFFFFFFFu, pr_, 2);
        pz_ += __shfl_xor_sync(0xFFFFFFFFu, pz_, 2);
        pn_ += __shfl_xor_sync(0xFFFFFFFFu, pn_, 2);

        const float hr = pr_ + bhr;
        const float hz = pz_ + bhz;
        const float hn = pn_ + bhn;
        const float hprev = sH[(size_t)(cur * 2 + b_loc) * LDW + posu];

        const float rg = 1.f / (1.f + expf(-(xr + hr)));
        const float zg = 1.f / (1.f + expf(-(xz + hz)));
        const float ng = tanhf(xn + rg * hn);
        const float hnew = ng + zg * (hprev - ng);

        // Each kq lane stores hnew to peer CTA kq's next-phase buffer.
        const uint32_t off =
            (uint32_t)((((cur ^ 1) * 2 + b_loc) * LDW + posu) * 4);
        asm volatile("st.shared::cluster.f32 [%0], %1;"
                     :: "r"(peer + off), "f"(hnew) : "memory");

        if (kq == 0) {
            outA[oa] = hnew;
        } else if (kq == 1 && doB) {
            outB[ob] = hnew;
        }
        oa += (size_t)ldA;
        ob += (size_t)ldB;
        xgp += G3;

        // Release my DSMEM writes / acquire peers' writes for the next step.
        asm volatile("barrier.cluster.arrive.aligned;" ::: "memory");
        asm volatile("barrier.cluster.wait.aligned;" ::: "memory");
        cur ^= 1;
    }
}

// ---------------------------------------------------------------------------
// Launch: gemm(xg0) -> recur L0 (h1 into concat[:, :, 0:256])
//         gemm(xg1 from h1) -> recur L1 (h2 into out_h2 and concat[:, :, 256:512])
// Output layout: [h2 (B,S,H)] then [concat(h1,h2) (B,S,2H)].
// ---------------------------------------------------------------------------
extern "C" void kernel_launch(void* const* d_in, const int* in_sizes, int n_in,
                              void* d_out, int out_size)
{
    (void)in_sizes; (void)n_in; (void)out_size;
    const float* inputs = (const float*)d_in[0];
    const float* W_ih0  = (const float*)d_in[1];
    const float* W_hh0  = (const float*)d_in[2];
    const float* b_ih0  = (const float*)d_in[3];
    const float* b_hh0  = (const float*)d_in[4];
    const float* W_ih1  = (const float*)d_in[5];
    const float* W_hh1  = (const float*)d_in[6];
    const float* b_ih1  = (const float*)d_in[7];
    const float* b_hh1  = (const float*)d_in[8];

    float* out_h2  = (float*)d_out;                            // [B,S,H]
    float* out_cat = out_h2 + (size_t)Bz * Sz * Hz;            // [B,S,2H]

    cudaFuncSetAttribute(gru_recur, cudaFuncAttributeMaxDynamicSharedMemorySize,
                         SMEM_BYTES);

    dim3 ggrid(G3 / 64, (Bz * Sz) / 64);  // (12, 1024)

    // Layer 0
    gemm_nt_bias<<<ggrid, 256>>>(inputs, 256, W_ih0, b_ih0);
    gru_recur<<<128, 512, SMEM_BYTES>>>(W_hh0, b_hh0,
                                        out_cat, 2 * Hz,       // h1 -> concat[:, :, 0:H]
                                        nullptr, 0);
    // Layer 1 (input = h1, strided inside concat)
    gemm_nt_bias<<<ggrid, 256>>>(out_cat, 2 * Hz, W_ih1, b_ih1);
    gru_recur<<<128, 512, SMEM_BYTES>>>(W_hh1, b_hh1,
                                        out_cat + Hz, 2 * Hz,  // h2 -> concat[:, :, H:2H]
                                        out_h2, Hz);           // h2 -> primary output
}

// round 12
// speedup vs baseline: 2.2441x; 1.2199x over previous
#include <cuda_runtime.h>
#include <cuda_bf16.h>
#include <cstdint>

// Problem constants
static constexpr int Bz = 64;     // batch
static constexpr int Sz = 1024;   // seq len
static constexpr int Hz = 256;    // hidden
static constexpr int G3 = 768;    // 3*H gate rows

// Recurrence geometry: 32 clusters x 4 CTAs = 128 CTAs; each cluster = 2 batches.
// CTA rank owns h-units [64*rank, 64*rank+64). 512 threads = (u_loc 0..63, kq 0..7).
// Weights live in REGISTERS: each thread holds W_hh rows {u_glob, 256+u_glob,
// 512+u_glob} restricted to k in [kq*32, kq*32+32) -> 96 f32 regs.
// Both batches are processed in-thread (interleaved accumulators).
//
// h state in smem, padded: k position j -> (j>>5)*36 + (j&31), row stride
// LDH = 288 floats. Lane kq's chunk starts at kq*36 floats = kq*9 (16B units)
// -> distinct mod 8 for kq 0..7 -> conflict-free LDS.128 (u lanes broadcast).
static constexpr int LDH = 288;
static constexpr int SH_FLOATS = 2 * 2 * LDH;   // [phase][batch][LDH]

// Scratch for precomputed input-side gate projections xg = x @ W_ih^T + b_ih  [B,S,3H]
__device__ float g_xg[(size_t)Bz * Sz * G3];

typedef unsigned long long u64;

__device__ __forceinline__ u64 fma2(u64 a, u64 b, u64 c) {
    u64 d;
    asm("fma.rn.f32x2 %0, %1, %2, %3;" : "=l"(d) : "l"(a), "l"(b), "l"(c));
    return d;
}
__device__ __forceinline__ float f2lo(u64 v) { return __uint_as_float((unsigned)v); }
__device__ __forceinline__ float f2hi(u64 v) { return __uint_as_float((unsigned)(v >> 32)); }
__device__ __forceinline__ u64 dup2(float a) {
    unsigned ai = __float_as_uint(a);
    u64 d;
    asm("mov.b64 %0, {%1, %2};" : "=l"(d) : "r"(ai), "r"(ai));
    return d;
}

// ---------------------------------------------------------------------------
// GEMM: g_xg[m, 0:768] = A[m, 0:256] @ W[768, 256]^T + bias   (unchanged)
// ---------------------------------------------------------------------------
__global__ __launch_bounds__(256) void gemm_nt_bias(
    const float* __restrict__ A, int lda,
    const float* __restrict__ W,
    const float* __restrict__ bias)
{
    __shared__ __align__(16) float As[32][68];  // As[k][m]
    __shared__ __align__(16) float Ws[32][68];  // Ws[k][n]

    const int tid = threadIdx.x;
    const int tx = tid & 15;
    const int ty = tid >> 4;
    const int m0 = blockIdx.y * 64;
    const int n0 = blockIdx.x * 64;

    u64 c00 = 0, c01 = 0, c10 = 0, c11 = 0, c20 = 0, c21 = 0, c30 = 0, c31 = 0;

    const int lrow = tid >> 3;
    const int lc4  = tid & 7;

    for (int k0 = 0; k0 < 256; k0 += 32) {
#pragma unroll
        for (int h = 0; h < 2; ++h) {
            const int row = lrow + h * 32;
            float4 va = *(const float4*)(A + (size_t)(m0 + row) * lda + k0 + lc4 * 4);
            As[lc4 * 4 + 0][row] = va.x;
            As[lc4 * 4 + 1][row] = va.y;
            As[lc4 * 4 + 2][row] = va.z;
            As[lc4 * 4 + 3][row] = va.w;
            float4 vw = *(const float4*)(W + (size_t)(n0 + row) * 256 + k0 + lc4 * 4);
            Ws[lc4 * 4 + 0][row] = vw.x;
            Ws[lc4 * 4 + 1][row] = vw.y;
            Ws[lc4 * 4 + 2][row] = vw.z;
            Ws[lc4 * 4 + 3][row] = vw.w;
        }
        __syncthreads();
#pragma unroll 8
        for (int kk = 0; kk < 32; ++kk) {
            float4 a4 = *(const float4*)&As[kk][ty * 4];
            ulonglong2 w4 = *(const ulonglong2*)&Ws[kk][tx * 4];
            u64 d0 = dup2(a4.x), d1 = dup2(a4.y), d2 = dup2(a4.z), d3 = dup2(a4.w);
            c00 = fma2(d0, w4.x, c00); c01 = fma2(d0, w4.y, c01);
            c10 = fma2(d1, w4.x, c10); c11 = fma2(d1, w4.y, c11);
            c20 = fma2(d2, w4.x, c20); c21 = fma2(d2, w4.y, c21);
            c30 = fma2(d3, w4.x, c30); c31 = fma2(d3, w4.y, c31);
        }
        __syncthreads();
    }

    const float4 bb = *(const float4*)(bias + n0 + tx * 4);
    float* Cbase = g_xg + (size_t)(m0 + ty * 4) * G3 + n0 + tx * 4;
    {
        float4 o;
        o.x = f2lo(c00) + bb.x; o.y = f2hi(c00) + bb.y;
        o.z = f2lo(c01) + bb.z; o.w = f2hi(c01) + bb.w;
        *(float4*)(Cbase + 0 * G3) = o;
    }
    {
        float4 o;
        o.x = f2lo(c10) + bb.x; o.y = f2hi(c10) + bb.y;
        o.z = f2lo(c11) + bb.z; o.w = f2hi(c11) + bb.w;
        *(float4*)(Cbase + 1 * G3) = o;
    }
    {
        float4 o;
        o.x = f2lo(c20) + bb.x; o.y = f2hi(c20) + bb.y;
        o.z = f2lo(c21) + bb.z; o.w = f2hi(c21) + bb.w;
        *(float4*)(Cbase + 2 * G3) = o;
    }
    {
        float4 o;
        o.x = f2lo(c30) + bb.x; o.y = f2hi(c30) + bb.y;
        o.z = f2lo(c31) + bb.z; o.w = f2hi(c31) + bb.w;
        *(float4*)(Cbase + 3 * G3) = o;
    }
}

// Map h position j (0..255) to padded float offset.
__device__ __forceinline__ int padposH(int j) { return (j >> 5) * 36 + (j & 31); }

// ---------------------------------------------------------------------------
// Recurrence with register-resident weights.
// Lane roles per (u): after the 3-round butterfly every kq lane has the full
// dots for both batches and computes both hnew values.
//   DSMEM: kq 0..3 store batch0's hnew to peer CTA kq; kq 4..7 store batch1's
//          hnew to peer CTA kq-4.
//   GMEM:  kq0 -> outA(b0), kq1 -> outA(b1), kq2 -> outB(b0), kq3 -> outB(b1).
// One 4-CTA barrier.cluster per step (release/acquire for DSMEM h writes).
// ---------------------------------------------------------------------------
__global__ __launch_bounds__(512, 1) __cluster_dims__(4, 1, 1)
void gru_recur(const float* __restrict__ Whh, const float* __restrict__ bhh,
               float* __restrict__ outA, int ldA,
               float* __restrict__ outB, int ldB)
{
    __shared__ __align__(16) float sH[SH_FLOATS];   // [2 phase][2 batch][LDH]

    const int tid = threadIdx.x;
    uint32_t rank;
    asm("mov.u32 %0, %%cluster_ctarank;" : "=r"(rank));
    const int kq    = tid & 7;             // k-eighth
    const int u_loc = tid >> 3;            // 0..63
    const int u_glob = (int)rank * 64 + u_loc;
    const int pu = padposH(u_glob);
    const int batch0 = (blockIdx.x >> 2) * 2;

    // ---- weights -> registers (one-time) ----
    ulonglong2 wr[8], wz[8], wn[8];
    {
        const ulonglong2* pr =
            (const ulonglong2*)(Whh + (size_t)(u_glob) * 256 + kq * 32);
        const ulonglong2* pz =
            (const ulonglong2*)(Whh + (size_t)(256 + u_glob) * 256 + kq * 32);
        const ulonglong2* pn =
            (const ulonglong2*)(Whh + (size_t)(512 + u_glob) * 256 + kq * 32);
#pragma unroll
        for (int kk = 0; kk < 8; ++kk) {
            wr[kk] = pr[kk];
            wz[kk] = pz[kk];
            wn[kk] = pn[kk];
        }
    }
    const float bhr = bhh[u_glob];
    const float bhz = bhh[256 + u_glob];
    const float bhn = bhh[512 + u_glob];

    for (int i = tid; i < SH_FLOATS; i += 512) sH[i] = 0.f;
    __syncthreads();
    asm volatile("barrier.cluster.arrive.aligned;" ::: "memory");
    asm volatile("barrier.cluster.wait.aligned;" ::: "memory");

    // Streams / outputs
    const float* xg0 = g_xg + ((size_t)batch0 * Sz) * G3 + u_glob;  // batch0
    // batch1 = xg0 + Sz*G3 (constant offset)
    float* op = nullptr;
    int ldo = 0;
    if (kq == 0 && outA) { op = outA + ((size_t)batch0 * Sz) * ldA + u_glob; ldo = ldA; }
    if (kq == 1 && outA) { op = outA + ((size_t)(batch0 + 1) * Sz) * ldA + u_glob; ldo = ldA; }
    if (kq == 2 && outB) { op = outB + ((size_t)batch0 * Sz) * ldB + u_glob; ldo = ldB; }
    if (kq == 3 && outB) { op = outB + ((size_t)(batch0 + 1) * Sz) * ldB + u_glob; ldo = ldB; }

    // Peer base address of sH in CTA (kq & 3), hoisted.
    uint32_t peer;
    {
        uint32_t b_;
        asm("{ .reg .u64 t; cvta.to.shared.u64 t, %1; cvt.u32.u64 %0, t; }"
            : "=r"(b_) : "l"((const float*)sH));
        asm("mapa.shared::cluster.u32 %0, %1, %2;"
            : "=r"(peer) : "r"(b_), "r"((uint32_t)(kq & 3)));
    }
    const int sbatch = kq >> 2;            // which batch this lane broadcasts

    int cur = 0;
    for (int s = 0; s < Sz; ++s) {
        // Input-side gate values for both batches (issued early; latency hidden).
        const float xr0 = __ldg(xg0);
        const float xz0 = __ldg(xg0 + 256);
        const float xn0 = __ldg(xg0 + 512);
        const float xr1 = __ldg(xg0 + (size_t)Sz * G3);
        const float xz1 = __ldg(xg0 + (size_t)Sz * G3 + 256);
        const float xn1 = __ldg(xg0 + (size_t)Sz * G3 + 512);

        // h chunks for this lane's k-eighth (32 floats = 8 x 16B, contiguous).
        const ulonglong2* hv0 =
            (const ulonglong2*)(sH + (size_t)(cur * 2 + 0) * LDH + kq * 36);
        const ulonglong2* hv1 =
            (const ulonglong2*)(sH + (size_t)(cur * 2 + 1) * LDH + kq * 36);

        u64 ar0 = 0, az0 = 0, an0 = 0, ar1 = 0, az1 = 0, an1 = 0;
#pragma unroll
        for (int kk = 0; kk < 8; ++kk) {
            const ulonglong2 h0 = hv0[kk];
            const ulonglong2 h1 = hv1[kk];
            ulonglong2 w;
            w = wr[kk];
            ar0 = fma2(w.x, h0.x, ar0); ar0 = fma2(w.y, h0.y, ar0);
            ar1 = fma2(w.x, h1.x, ar1); ar1 = fma2(w.y, h1.y, ar1);
            w = wz[kk];
            az0 = fma2(w.x, h0.x, az0); az0 = fma2(w.y, h0.y, az0);
            az1 = fma2(w.x, h1.x, az1); az1 = fma2(w.y, h1.y, az1);
            w = wn[kk];
            an0 = fma2(w.x, h0.x, an0); an0 = fma2(w.y, h0.y, an0);
            an1 = fma2(w.x, h1.x, an1); an1 = fma2(w.y, h1.y, an1);
        }
        // Partial -> full dots via 3-round butterfly over the 8 kq lanes.
        float pr0 = f2lo(ar0) + f2hi(ar0), pz0 = f2lo(az0) + f2hi(az0);
        float pn0 = f2lo(an0) + f2hi(an0);
        float pr1 = f2lo(ar1) + f2hi(ar1), pz1 = f2lo(az1) + f2hi(az1);
        float pn1 = f2lo(an1) + f2hi(an1);
#pragma unroll
        for (int m = 1; m < 8; m <<= 1) {
            pr0 += __shfl_xor_sync(0xFFFFFFFFu, pr0, m);
            pz0 += __shfl_xor_sync(0xFFFFFFFFu, pz0, m);
            pn0 += __shfl_xor_sync(0xFFFFFFFFu, pn0, m);
            pr1 += __shfl_xor_sync(0xFFFFFFFFu, pr1, m);
            pz1 += __shfl_xor_sync(0xFFFFFFFFu, pz1, m);
            pn1 += __shfl_xor_sync(0xFFFFFFFFu, pn1, m);
        }

        const float hprev0 = sH[(size_t)(cur * 2 + 0) * LDH + pu];
        const float hprev1 = sH[(size_t)(cur * 2 + 1) * LDH + pu];

        const float rg0 = 1.f / (1.f + expf(-(xr0 + pr0 + bhr)));
        const float zg0 = 1.f / (1.f + expf(-(xz0 + pz0 + bhz)));
        const float ng0 = tanhf(xn0 + rg0 * (pn0 + bhn));
        const float hnew0 = ng0 + zg0 * (hprev0 - ng0);

        const float rg1 = 1.f / (1.f + expf(-(xr1 + pr1 + bhr)));
        const float zg1 = 1.f / (1.f + expf(-(xz1 + pz1 + bhz)));
        const float ng1 = tanhf(xn1 + rg1 * (pn1 + bhn));
        const float hnew1 = ng1 + zg1 * (hprev1 - ng1);

        // DSMEM broadcast: lane stores its assigned batch's hnew to peer (kq&3).
        const float hb = sbatch ? hnew1 : hnew0;
        const uint32_t off =
            (uint32_t)((((cur ^ 1) * 2 + sbatch) * LDH + pu) * 4);
        asm volatile("st.shared::cluster.f32 [%0], %1;"
                     :: "r"(peer + off), "f"(hb) : "memory");

        if (op) {
            *op = (kq & 1) ? hnew1 : hnew0;
            op += ldo;
        }
        xg0 += G3;

        // Release my DSMEM write / acquire peers' writes for the next step.
        asm volatile("barrier.cluster.arrive.aligned;" ::: "memory");
        asm volatile("barrier.cluster.wait.aligned;" ::: "memory");
        cur ^= 1;
    }
}

// ---------------------------------------------------------------------------
// Launch: gemm(xg0) -> recur L0 (h1 into concat[:, :, 0:256])
//         gemm(xg1 from h1) -> recur L1 (h2 into out_h2 and concat[:, :, 256:512])
// Output layout: [h2 (B,S,H)] then [concat(h1,h2) (B,S,2H)].
// ---------------------------------------------------------------------------
extern "C" void kernel_launch(void* const* d_in, const int* in_sizes, int n_in,
                              void* d_out, int out_size)
{
    (void)in_sizes; (void)n_in; (void)out_size;
    const float* inputs = (const float*)d_in[0];
    const float* W_ih0  = (const float*)d_in[1];
    const float* W_hh0  = (const float*)d_in[2];
    const float* b_ih0  = (const float*)d_in[3];
    const float* b_hh0  = (const float*)d_in[4];
    const float* W_ih1  = (const float*)d_in[5];
    const float* W_hh1  = (const float*)d_in[6];
    const float* b_ih1  = (const float*)d_in[7];
    const float* b_hh1  = (const float*)d_in[8];

    float* out_h2  = (float*)d_out;                            // [B,S,H]
    float* out_cat = out_h2 + (size_t)Bz * Sz * Hz;            // [B,S,2H]

    dim3 ggrid(G3 / 64, (Bz * Sz) / 64);  // (12, 1024)

    // Layer 0
    gemm_nt_bias<<<ggrid, 256>>>(inputs, 256, W_ih0, b_ih0);
    gru_recur<<<128, 512>>>(W_hh0, b_hh0,
                            out_cat, 2 * Hz,        // h1 -> concat[:, :, 0:H]
                            nullptr, 0);
    // Layer 1 (input = h1, strided inside concat)
    gemm_nt_bias<<<ggrid, 256>>>(out_cat, 2 * Hz, W_ih1, b_ih1);
    gru_recur<<<128, 512>>>(W_hh1, b_hh1,
                            out_cat + Hz, 2 * Hz,   // h2 -> concat[:, :, H:2H]
                            out_h2, Hz);            // h2 -> primary output
}

// round 13
// speedup vs baseline: 3.5860x; 1.5980x over previous
#include <cuda_runtime.h>
#include <cuda_bf16.h>
#include <cstdint>

// Problem constants
static constexpr int Bz = 64;     // batch
static constexpr int Sz = 1024;   // seq len
static constexpr int Hz = 256;    // hidden
static constexpr int G3 = 768;    // 3*H gate rows

// Recurrence geometry: 32 clusters x 4 CTAs = 128 CTAs; each cluster = 2 batches.
// CTA rank owns h-units [64*rank, 64*rank+64). 512 threads = (u_loc 0..63, kq 0..7).
// Weights in registers: thread holds W_hh rows {u_glob, 256+u_glob, 512+u_glob}
// restricted to k in [kq*32, kq*32+32) -> 96 f32 regs.
//
// h state: TRIPLE-buffered in smem (stage = s % 3), padded layout:
// k position j -> (j>>5)*36 + (j&31); row stride LDH = 288 floats. Lane kq's
// 32-float chunk starts at kq*36 floats = kq*9 16B-units -> distinct mod 8
// -> conflict-free LDS.128 (u lanes broadcast).
//
// Sync: per-stage mbarrier with tx counting. Each step, 512 st.async stores
// (4 bytes each) target each CTA's next-stage buffer + mbarrier; consumer
// waits parity on its local stage mbarrier (expect_tx = 2048 bytes, arrive
// count = 1 via the re-arm thread). Skew between CTAs is provably <= 1 step,
// so 3 stages eliminate the read-antidependence a full barrier used to cover.
static constexpr int LDH = 288;
static constexpr int NSTAGE = 3;
static constexpr int STEP_TX_BYTES = 512 * 4;   // 2 batches x 256 h x 4B

// Scratch for precomputed input-side gate projections xg = x @ W_ih^T + b_ih  [B,S,3H]
__device__ float g_xg[(size_t)Bz * Sz * G3];

typedef unsigned long long u64;

__device__ __forceinline__ u64 fma2(u64 a, u64 b, u64 c) {
    u64 d;
    asm("fma.rn.f32x2 %0, %1, %2, %3;" : "=l"(d) : "l"(a), "l"(b), "l"(c));
    return d;
}
__device__ __forceinline__ float f2lo(u64 v) { return __uint_as_float((unsigned)v); }
__device__ __forceinline__ float f2hi(u64 v) { return __uint_as_float((unsigned)(v >> 32)); }
__device__ __forceinline__ u64 dup2(float a) {
    unsigned ai = __float_as_uint(a);
    u64 d;
    asm("mov.b64 %0, {%1, %2};" : "=l"(d) : "r"(ai), "r"(ai));
    return d;
}

__device__ __forceinline__ uint32_t smem_u32(const void* p) {
    uint32_t r;
    asm("{ .reg .u64 t; cvta.to.shared.u64 t, %1; cvt.u32.u64 %0, t; }"
        : "=r"(r) : "l"(p));
    return r;
}

__device__ __forceinline__ void mbar_wait_parity_acq(uint32_t mbar, uint32_t par) {
    uint32_t done;
    asm volatile(
        "{\n\t.reg .pred p;\n\t"
        "mbarrier.try_wait.parity.acquire.cluster.shared::cta.b64 p, [%1], %2;\n\t"
        "selp.b32 %0, 1, 0, p;\n\t}"
        : "=r"(done) : "r"(mbar), "r"(par) : "memory");
    while (!done) {
        asm volatile(
            "{\n\t.reg .pred p;\n\t"
            "mbarrier.try_wait.parity.acquire.cluster.shared::cta.b64 p, [%1], %2, 0x989680;\n\t"
            "selp.b32 %0, 1, 0, p;\n\t}"
            : "=r"(done) : "r"(mbar), "r"(par) : "memory");
    }
}

// ---------------------------------------------------------------------------
// GEMM: g_xg[m, 0:768] = A[m, 0:256] @ W[768, 256]^T + bias   (unchanged)
// ---------------------------------------------------------------------------
__global__ __launch_bounds__(256) void gemm_nt_bias(
    const float* __restrict__ A, int lda,
    const float* __restrict__ W,
    const float* __restrict__ bias)
{
    __shared__ __align__(16) float As[32][68];  // As[k][m]
    __shared__ __align__(16) float Ws[32][68];  // Ws[k][n]

    const int tid = threadIdx.x;
    const int tx = tid & 15;
    const int ty = tid >> 4;
    const int m0 = blockIdx.y * 64;
    const int n0 = blockIdx.x * 64;

    u64 c00 = 0, c01 = 0, c10 = 0, c11 = 0, c20 = 0, c21 = 0, c30 = 0, c31 = 0;

    const int lrow = tid >> 3;
    const int lc4  = tid & 7;

    for (int k0 = 0; k0 < 256; k0 += 32) {
#pragma unroll
        for (int h = 0; h < 2; ++h) {
            const int row = lrow + h * 32;
            float4 va = *(const float4*)(A + (size_t)(m0 + row) * lda + k0 + lc4 * 4);
            As[lc4 * 4 + 0][row] = va.x;
            As[lc4 * 4 + 1][row] = va.y;
            As[lc4 * 4 + 2][row] = va.z;
            As[lc4 * 4 + 3][row] = va.w;
            float4 vw = *(const float4*)(W + (size_t)(n0 + row) * 256 + k0 + lc4 * 4);
            Ws[lc4 * 4 + 0][row] = vw.x;
            Ws[lc4 * 4 + 1][row] = vw.y;
            Ws[lc4 * 4 + 2][row] = vw.z;
            Ws[lc4 * 4 + 3][row] = vw.w;
        }
        __syncthreads();
#pragma unroll 8
        for (int kk = 0; kk < 32; ++kk) {
            float4 a4 = *(const float4*)&As[kk][ty * 4];
            ulonglong2 w4 = *(const ulonglong2*)&Ws[kk][tx * 4];
            u64 d0 = dup2(a4.x), d1 = dup2(a4.y), d2 = dup2(a4.z), d3 = dup2(a4.w);
            c00 = fma2(d0, w4.x, c00); c01 = fma2(d0, w4.y, c01);
            c10 = fma2(d1, w4.x, c10); c11 = fma2(d1, w4.y, c11);
            c20 = fma2(d2, w4.x, c20); c21 = fma2(d2, w4.y, c21);
            c30 = fma2(d3, w4.x, c30); c31 = fma2(d3, w4.y, c31);
        }
        __syncthreads();
    }

    const float4 bb = *(const float4*)(bias + n0 + tx * 4);
    float* Cbase = g_xg + (size_t)(m0 + ty * 4) * G3 + n0 + tx * 4;
    {
        float4 o;
        o.x = f2lo(c00) + bb.x; o.y = f2hi(c00) + bb.y;
        o.z = f2lo(c01) + bb.z; o.w = f2hi(c01) + bb.w;
        *(float4*)(Cbase + 0 * G3) = o;
    }
    {
        float4 o;
        o.x = f2lo(c10) + bb.x; o.y = f2hi(c10) + bb.y;
        o.z = f2lo(c11) + bb.z; o.w = f2hi(c11) + bb.w;
        *(float4*)(Cbase + 1 * G3) = o;
    }
    {
        float4 o;
        o.x = f2lo(c20) + bb.x; o.y = f2hi(c20) + bb.y;
        o.z = f2lo(c21) + bb.z; o.w = f2hi(c21) + bb.w;
        *(float4*)(Cbase + 2 * G3) = o;
    }
    {
        float4 o;
        o.x = f2lo(c30) + bb.x; o.y = f2hi(c30) + bb.y;
        o.z = f2lo(c31) + bb.z; o.w = f2hi(c31) + bb.w;
        *(float4*)(Cbase + 3 * G3) = o;
    }
}

// Map h position j (0..255) to padded float offset.
__device__ __forceinline__ int padposH(int j) { return (j >> 5) * 36 + (j & 31); }

// ---------------------------------------------------------------------------
// Recurrence: register weights + st.async/mbarrier pipelined cluster sync.
// After the dot, a cross-batch exchange (xor 4) gives lanes kq<4 batch0 and
// lanes kq>=4 batch1; 2 butterfly rounds finish the reduction (9 shfl total).
// Each lane computes gates for ITS batch only, st.async's hnew to peer (kq&3)
// next-stage buffer (+4B tx to that peer's stage mbarrier).
// Outputs: kq0->outA(b0), kq4->outA(b1), kq2->outB(b0), kq6->outB(b1).
// ---------------------------------------------------------------------------
__global__ __launch_bounds__(512, 1) __cluster_dims__(4, 1, 1)
void gru_recur(const float* __restrict__ Whh, const float* __restrict__ bhh,
               float* __restrict__ outA, int ldA,
               float* __restrict__ outB, int ldB)
{
    __shared__ __align__(16) float sH[NSTAGE * 2 * LDH];  // [stage][batch][LDH]
    __shared__ __align__(8) unsigned long long mb[NSTAGE];

    const int tid = threadIdx.x;
    uint32_t rank;
    asm("mov.u32 %0, %%cluster_ctarank;" : "=r"(rank));
    const int kq    = tid & 7;             // k-eighth
    const int u_loc = tid >> 3;            // 0..63
    const int u_glob = (int)rank * 64 + u_loc;
    const int pu = padposH(u_glob);
    const int batch0 = (blockIdx.x >> 2) * 2;
    const int sbatch = kq >> 2;            // this lane's batch (0/1)

    // ---- weights -> registers (one-time) ----
    ulonglong2 wr[8], wz[8], wn[8];
    {
        const ulonglong2* pr =
            (const ulonglong2*)(Whh + (size_t)(u_glob) * 256 + kq * 32);
        const ulonglong2* pz =
            (const ulonglong2*)(Whh + (size_t)(256 + u_glob) * 256 + kq * 32);
        const ulonglong2* pn =
            (const ulonglong2*)(Whh + (size_t)(512 + u_glob) * 256 + kq * 32);
#pragma unroll
        for (int kk = 0; kk < 8; ++kk) {
            wr[kk] = pr[kk];
            wz[kk] = pz[kk];
            wn[kk] = pn[kk];
        }
    }
    const float bhr = bhh[u_glob];
    const float bhz = bhh[256 + u_glob];
    const float bhn = bhh[512 + u_glob];

    for (int i = tid; i < NSTAGE * 2 * LDH; i += 512) sH[i] = 0.f;

    const uint32_t sH_u32 = smem_u32(sH);
    const uint32_t mb_u32 = smem_u32(mb);

    if (tid == 0) {
#pragma unroll
        for (int j = 0; j < NSTAGE; ++j) {
            asm volatile("mbarrier.init.shared.b64 [%0], 1;"
                         :: "r"(mb_u32 + j * 8) : "memory");
        }
        // Stage 0 completes immediately (zero-filled h is the step-0 input);
        // stages 1,2 await the tx from steps 0,1.
        asm volatile("mbarrier.arrive.expect_tx.shared.b64 _, [%0], 0;"
                     :: "r"(mb_u32 + 0) : "memory");
        asm volatile("mbarrier.arrive.expect_tx.shared.b64 _, [%0], %1;"
                     :: "r"(mb_u32 + 8), "r"(STEP_TX_BYTES) : "memory");
        asm volatile("mbarrier.arrive.expect_tx.shared.b64 _, [%0], %1;"
                     :: "r"(mb_u32 + 16), "r"(STEP_TX_BYTES) : "memory");
    }
    __syncthreads();
    asm volatile("barrier.cluster.arrive.aligned;" ::: "memory");
    asm volatile("barrier.cluster.wait.aligned;" ::: "memory");

    // Peer (kq&3) addresses, hoisted.
    uint32_t peer_sH, peer_mb[NSTAGE];
    asm("mapa.shared::cluster.u32 %0, %1, %2;"
        : "=r"(peer_sH) : "r"(sH_u32), "r"((uint32_t)(kq & 3)));
#pragma unroll
    for (int j = 0; j < NSTAGE; ++j) {
        asm("mapa.shared::cluster.u32 %0, %1, %2;"
            : "=r"(peer_mb[j]) : "r"(mb_u32 + j * 8), "r"((uint32_t)(kq & 3)));
    }

    // xg stream for this lane's batch only.
    const float* xgp = g_xg + ((size_t)(batch0 + sbatch) * Sz) * G3 + u_glob;

    // Output pointer for this lane (or null).
    float* op = nullptr;
    int ldo = 0;
    if (kq == 0 && outA) { op = outA + ((size_t)batch0 * Sz) * ldA + u_glob; ldo = ldA; }
    if (kq == 4 && outA) { op = outA + ((size_t)(batch0 + 1) * Sz) * ldA + u_glob; ldo = ldA; }
    if (kq == 2 && outB) { op = outB + ((size_t)batch0 * Sz) * ldB + u_glob; ldo = ldB; }
    if (kq == 6 && outB) { op = outB + ((size_t)(batch0 + 1) * Sz) * ldB + u_glob; ldo = ldB; }

    // Preload xg for step 0.
    float xr = __ldg(xgp);
    float xz = __ldg(xgp + 256);
    float xn = __ldg(xgp + 512);

    int st_cur = 0, st_next = 1;
    unsigned ph = 0;  // parity bits per stage

    for (int s = 0; s < Sz; ++s) {
        // Prefetch next step's xg (issued before the wait; hides L2 latency).
        const float* xn_p = (s + 1 < Sz) ? (xgp + G3) : xgp;
        const float nxr = __ldg(xn_p);
        const float nxz = __ldg(xn_p + 256);
        const float nxn = __ldg(xn_p + 512);

        // Wait for this step's h state (tx-complete, acquire).
        mbar_wait_parity_acq(mb_u32 + st_cur * 8, (ph >> st_cur) & 1u);
        ph ^= (1u << st_cur);
        if (tid == 0) {
            // Re-arm this stage for its next use (step s+3).
            asm volatile("mbarrier.arrive.expect_tx.shared.b64 _, [%0], %1;"
                         :: "r"(mb_u32 + st_cur * 8), "r"(STEP_TX_BYTES) : "memory");
        }

        // Dot products over both batches' h (smem, conflict-free).
        const ulonglong2* hv0 =
            (const ulonglong2*)(sH + (size_t)(st_cur * 2 + 0) * LDH + kq * 36);
        const ulonglong2* hv1 =
            (const ulonglong2*)(sH + (size_t)(st_cur * 2 + 1) * LDH + kq * 36);

        u64 ar0 = 0, az0 = 0, an0 = 0, ar1 = 0, az1 = 0, an1 = 0;
#pragma unroll
        for (int kk = 0; kk < 8; ++kk) {
            const ulonglong2 h0 = hv0[kk];
            const ulonglong2 h1 = hv1[kk];
            ulonglong2 w;
            w = wr[kk];
            ar0 = fma2(w.x, h0.x, ar0); ar0 = fma2(w.y, h0.y, ar0);
            ar1 = fma2(w.x, h1.x, ar1); ar1 = fma2(w.y, h1.y, ar1);
            w = wz[kk];
            az0 = fma2(w.x, h0.x, az0); az0 = fma2(w.y, h0.y, az0);
            az1 = fma2(w.x, h1.x, az1); az1 = fma2(w.y, h1.y, az1);
            w = wn[kk];
            an0 = fma2(w.x, h0.x, an0); an0 = fma2(w.y, h0.y, an0);
            an1 = fma2(w.x, h1.x, an1); an1 = fma2(w.y, h1.y, an1);
        }
        float pr0 = f2lo(ar0) + f2hi(ar0), pz0 = f2lo(az0) + f2hi(az0);
        float pn0 = f2lo(an0) + f2hi(an0);
        float pr1 = f2lo(ar1) + f2hi(ar1), pz1 = f2lo(az1) + f2hi(az1);
        float pn1 = f2lo(an1) + f2hi(an1);

        // Cross-batch exchange (xor 4): keep own batch, receive partner's
        // partial of the same batch. Then 2 butterfly rounds within 4 lanes.
        const float sr = sbatch ? pr0 : pr1;
        const float sz_ = sbatch ? pz0 : pz1;
        const float sn = sbatch ? pn0 : pn1;
        float fr = (sbatch ? pr1 : pr0) + __shfl_xor_sync(0xFFFFFFFFu, sr, 4);
        float fz = (sbatch ? pz1 : pz0) + __shfl_xor_sync(0xFFFFFFFFu, sz_, 4);
        float fn = (sbatch ? pn1 : pn0) + __shfl_xor_sync(0xFFFFFFFFu, sn, 4);
        fr += __shfl_xor_sync(0xFFFFFFFFu, fr, 1);
        fz += __shfl_xor_sync(0xFFFFFFFFu, fz, 1);
        fn += __shfl_xor_sync(0xFFFFFFFFu, fn, 1);
        fr += __shfl_xor_sync(0xFFFFFFFFu, fr, 2);
        fz += __shfl_xor_sync(0xFFFFFFFFu, fz, 2);
        fn += __shfl_xor_sync(0xFFFFFFFFu, fn, 2);

        // Gates for this lane's batch only.
        const float hprev = sH[(size_t)(st_cur * 2 + sbatch) * LDH + pu];
        const float rg = 1.f / (1.f + expf(-(xr + fr + bhr)));
        const float zg = 1.f / (1.f + expf(-(xz + fz + bhz)));
        const float ng = tanhf(xn + rg * (fn + bhn));
        const float hnew = ng + zg * (hprev - ng);

        // st.async: value + 4B tx to peer (kq&3)'s next-stage buffer/mbar.
        const uint32_t off =
            (uint32_t)(((st_next * 2 + sbatch) * LDH + pu) * 4);
        asm volatile(
            "st.async.shared::cluster.mbarrier::complete_tx::bytes.b32 [%0], %1, [%2];"
            :: "r"(peer_sH + off), "r"(__float_as_uint(hnew)),
               "r"(peer_mb[st_next]) : "memory");

        if (op) {
            *op = hnew;
            op += ldo;
        }

        xr = nxr; xz = nxz; xn = nxn;
        xgp += G3;
        st_cur = st_next;
        st_next = (st_next + 1 == NSTAGE) ? 0 : st_next + 1;
    }

    // Keep all CTAs alive until in-flight st.async traffic has landed.
    asm volatile("barrier.cluster.arrive.aligned;" ::: "memory");
    asm volatile("barrier.cluster.wait.aligned;" ::: "memory");
}

// ---------------------------------------------------------------------------
// Launch: gemm(xg0) -> recur L0 (h1 into concat[:, :, 0:256])
//         gemm(xg1 from h1) -> recur L1 (h2 into out_h2 and concat[:, :, 256:512])
// Output layout: [h2 (B,S,H)] then [concat(h1,h2) (B,S,2H)].
// ---------------------------------------------------------------------------
extern "C" void kernel_launch(void* const* d_in, const int* in_sizes, int n_in,
                              void* d_out, int out_size)
{
    (void)in_sizes; (void)n_in; (void)out_size;
    const float* inputs = (const float*)d_in[0];
    const float* W_ih0  = (const float*)d_in[1];
    const float* W_hh0  = (const float*)d_in[2];
    const float* b_ih0  = (const float*)d_in[3];
    const float* b_hh0  = (const float*)d_in[4];
    const float* W_ih1  = (const float*)d_in[5];
    const float* W_hh1  = (const float*)d_in[6];
    const float* b_ih1  = (const float*)d_in[7];
    const float* b_hh1  = (const float*)d_in[8];

    float* out_h2  = (float*)d_out;                            // [B,S,H]
    float* out_cat = out_h2 + (size_t)Bz * Sz * Hz;            // [B,S,2H]

    dim3 ggrid(G3 / 64, (Bz * Sz) / 64);  // (12, 1024)

    // Layer 0
    gemm_nt_bias<<<ggrid, 256>>>(inputs, 256, W_ih0, b_ih0);
    gru_recur<<<128, 512>>>(W_hh0, b_hh0,
                            out_cat, 2 * Hz,        // h1 -> concat[:, :, 0:H]
                            nullptr, 0);
    // Layer 1 (input = h1, strided inside concat)
    gemm_nt_bias<<<ggrid, 256>>>(out_cat, 2 * Hz, W_ih1, b_ih1);
    gru_recur<<<128, 512>>>(W_hh1, b_hh1,
                            out_cat + Hz, 2 * Hz,   // h2 -> concat[:, :, H:2H]
                            out_h2, Hz);            // h2 -> primary output
}